// round 7
// baseline (speedup 1.0000x reference)
#include <cuda_runtime.h>

// SSIM loss, fused separable 11x11 Gaussian, B=64, H=W=512.
// R7: TH=24 tiles + register diet -> 4 CTAs/SM (32 warps).
//     smem 49.9KB/CTA: interleaved input tile + plane-pair-interleaved v
//     (v01=(mu_x,mu_y), v23=(x2+y2, xy)); stage-C processes 2 output pairs
//     per unit with a 7-entry window so peak regs fit the 64-reg/4-CTA cap.

#define BATCH 64
#define IMG_H 512
#define IMG_W 512
#define TH 24
#define HALO 5
#define PH 34                 // TH + 10
#define NCP 38                // padded col-pairs (76 cols incl. 2 pad)
#define THREADS 256
#define TILES_X 8
#define TILES_Y 22            // 21 full + one 8-row partial
#define NBLOCKS (BATCH * TILES_X * TILES_Y)   // 11264

#define IN_BYTES  (PH * NCP * 16)     // 20672
#define VPP_BYTES (TH * NCP * 16)     // 14592 per plane-pair
#define SMEM_BYTES (IN_BYTES + 2 * VPP_BYTES)  // 49856

#define NSLOTS 32
#define SLOT_STRIDE 16

typedef unsigned long long u64;

// Gaussian(ks=11, sigma=1.5), normalized.
#define W0 0.00102838f
#define W1 0.00759876f
#define W2 0.03600077f
#define W3 0.10936069f
#define W4 0.21300553f
#define W5 0.26601172f
__device__ __constant__ float c_w[11] = {W0,W1,W2,W3,W4,W5,W4,W3,W2,W1,W0};

__device__ double g_slots[NSLOTS * SLOT_STRIDE];   // static zero-init

__device__ __forceinline__ unsigned smem_u32(const void* p) {
    unsigned r;
    asm("{ .reg .u64 t; cvta.to.shared.u64 t, %1; cvt.u32.u64 %0, t; }"
        : "=r"(r) : "l"(p));
    return r;
}
__device__ __forceinline__ u64 pack2(float lo, float hi) {
    u64 r; asm("mov.b64 %0, {%1,%2};" : "=l"(r) : "f"(lo), "f"(hi)); return r;
}
__device__ __forceinline__ void unpack2(u64 v, float& a, float& b) {
    asm("mov.b64 {%0,%1}, %2;" : "=f"(a), "=f"(b) : "l"(v));
}
__device__ __forceinline__ u64 swap2(u64 v) {
    u64 r;
    asm("{ .reg .b32 lo, hi; mov.b64 {lo,hi}, %1; mov.b64 %0, {hi,lo}; }"
        : "=l"(r) : "l"(v));
    return r;
}
__device__ __forceinline__ u64 fma2(u64 a, u64 b, u64 c) {
    u64 d; asm("fma.rn.f32x2 %0, %1, %2, %3;" : "=l"(d) : "l"(a), "l"(b), "l"(c));
    return d;
}
__device__ __forceinline__ u64 mul2(u64 a, u64 b) {
    u64 d; asm("mul.rn.f32x2 %0, %1, %2;" : "=l"(d) : "l"(a), "l"(b)); return d;
}
__device__ __forceinline__ u64 add2(u64 a, u64 b) {
    u64 d; asm("add.rn.f32x2 %0, %1, %2;" : "=l"(d) : "l"(a), "l"(b)); return d;
}
__device__ __forceinline__ void lds128(unsigned addr, u64& a, u64& b) {
    asm volatile("ld.shared.v2.b64 {%0,%1}, [%2];" : "=l"(a), "=l"(b) : "r"(addr));
}
__device__ __forceinline__ void sts128(unsigned addr, u64 a, u64 b) {
    asm volatile("st.shared.v2.b64 [%0], {%1,%2};" :: "r"(addr), "l"(a), "l"(b));
}

__global__ void ssim_zero_k() {
    g_slots[threadIdx.x * SLOT_STRIDE] = 0.0;
}

__global__ void ssim_finalize_k(float* out) {
    int t = threadIdx.x;
    double v = g_slots[t * SLOT_STRIDE];
    #pragma unroll
    for (int off = 16; off > 0; off >>= 1)
        v += __shfl_down_sync(0xFFFFFFFFu, v, off);
    if (t == 0)
        out[0] = (float)(1.0 - v / ((double)BATCH * IMG_H * IMG_W));
}

// 11-tap horizontal conv on packed pairs via even/odd accumulators.
// win points at 6 consecutive u64 window entries for this output pair.
__device__ __forceinline__ u64 hconv(const u64* win, const u64* wA, const u64* wB) {
    u64 acc = 0, accS = 0;
    #pragma unroll
    for (int i = 0; i < 6; i++) {
        acc  = fma2(wA[i], win[i], acc);
        accS = fma2(wB[i], win[i], accS);
    }
    return add2(acc, swap2(accS));
}

__global__ __launch_bounds__(THREADS, 4)
void ssim_main_k(const float* __restrict__ x, const float* __restrict__ y) {
    extern __shared__ float smem[];
    const unsigned sb   = smem_u32(smem);
    const unsigned vb01 = sb + IN_BYTES;
    const unsigned vb23 = vb01 + VPP_BYTES;

    const int tid = threadIdx.x;
    const int blk = blockIdx.x;
    const int b  = blk / (TILES_X * TILES_Y);
    const int t  = blk - b * (TILES_X * TILES_Y);
    const int ty = t >> 3;
    const int tx = t & 7;
    const int gx0 = tx * 64 - HALO;
    const int gy0 = ty * TH - HALO;

    const float* __restrict__ xb = x + (size_t)b * IMG_H * IMG_W;
    const float* __restrict__ yb = y + (size_t)b * IMG_H * IMG_W;

    // ---- Stage A: halo load into interleaved tile (x0,x1,y0,y1) ----
    {
        int r  = tid / NCP;
        int cp = tid - r * NCP;
        const bool interior = (gx0 >= 0) & (gy0 >= 0) &
                              (gx0 + 2 * NCP <= IMG_W) & (gy0 + PH <= IMG_H);
        if (interior) {
            const float* __restrict__ xr = xb + (size_t)gy0 * IMG_W + gx0;
            const float* __restrict__ yr = yb + (size_t)gy0 * IMG_W + gx0;
            for (int e = tid; e < PH * NCP; e += THREADS) {
                int off = r * IMG_W + 2 * cp;
                sts128(sb + (unsigned)(e << 4),
                       pack2(xr[off], xr[off + 1]),
                       pack2(yr[off], yr[off + 1]));
                r += 6; cp += (THREADS - 6 * NCP);
                if (cp >= NCP) { cp -= NCP; r += 1; }
            }
        } else {
            for (int e = tid; e < PH * NCP; e += THREADS) {
                int gy = gy0 + r;
                int g0 = gx0 + 2 * cp;
                float x0 = 0.f, x1 = 0.f, y0 = 0.f, y1 = 0.f;
                if ((unsigned)gy < IMG_H) {
                    size_t rowb = (size_t)gy * IMG_W;
                    if ((unsigned)g0 < IMG_W) { x0 = xb[rowb + g0]; y0 = yb[rowb + g0]; }
                    if ((unsigned)(g0 + 1) < IMG_W) { x1 = xb[rowb + g0 + 1]; y1 = yb[rowb + g0 + 1]; }
                }
                sts128(sb + (unsigned)(e << 4), pack2(x0, x1), pack2(y0, y1));
                r += 6; cp += (THREADS - 6 * NCP);
                if (cp >= NCP) { cp -= NCP; r += 1; }
            }
        }
    }
    __syncthreads();

    // ---- Stage B: vertical conv {x, y, x2+y2, xy}, 4-row strips, 228 items ----
    if (tid < 6 * NCP) {
        // symmetric packed weights: w[k] == w[10-k]
        u64 w2[6];
        #pragma unroll
        for (int k = 0; k < 6; k++) w2[k] = pack2(c_w[k], c_w[k]);

        int rs = tid / NCP;           // 0..5
        int cp = tid - rs * NCP;
        int r0 = rs * 4;
        unsigned in0 = sb + (unsigned)((r0 * NCP + cp) << 4);

        u64 s0[4] = {0,0,0,0};
        u64 s1[4] = {0,0,0,0};
        u64 s2[4] = {0,0,0,0};
        u64 s3[4] = {0,0,0,0};
        #pragma unroll
        for (int j = 0; j < 14; j++) {
            u64 a, bb;
            lds128(in0 + j * (NCP * 16), a, bb);
            u64 ab = mul2(a, bb);
            u64 qq = fma2(a, a, mul2(bb, bb));
            #pragma unroll
            for (int tt = 0; tt < 4; tt++) {
                int k = j - tt;
                if (k >= 0 && k <= 10) {
                    u64 wk = w2[(k <= 5) ? k : 10 - k];
                    s0[tt] = fma2(wk, a,  s0[tt]);
                    s1[tt] = fma2(wk, bb, s1[tt]);
                    s2[tt] = fma2(wk, qq, s2[tt]);
                    s3[tt] = fma2(wk, ab, s3[tt]);
                }
            }
        }
        #pragma unroll
        for (int tt = 0; tt < 4; tt++) {
            unsigned o = (unsigned)(((r0 + tt) * NCP + cp) << 4);
            sts128(vb01 + o, s0[tt], s1[tt]);
            sts128(vb23 + o, s2[tt], s3[tt]);
        }
    }
    __syncthreads();

    // ---- Stage C: horizontal conv + SSIM, units = 24 rows x 16 qblocks ----
    float lsum = 0.f;
    {
        u64 wA[6], wB[6];
        #pragma unroll
        for (int i = 0; i < 6; i++) {
            wA[i] = pack2(c_w[2 * i], c_w[2 * i]);
            float blo = (i >= 1) ? c_w[2 * i - 1] : 0.f;
            float bhi = (i <= 4) ? c_w[2 * i + 1] : 0.f;
            wB[i] = pack2(blo, bhi);
        }
        const u64 c1_2  = pack2(1e-4f, 1e-4f);
        const u64 c2_2  = pack2(9e-4f, 9e-4f);
        const u64 eps2  = pack2(1e-12f, 1e-12f);
        const u64 n1_2  = pack2(-1.f, -1.f);
        const u64 two_2 = pack2(2.f, 2.f);

        for (int e = tid; e < 24 * 16; e += THREADS) {
            int r  = e >> 4;
            int qb = e & 15;
            unsigned base = (unsigned)((r * NCP + 2 * qb) << 4);

            u64 a0[7], a1[7];
            #pragma unroll
            for (int i = 0; i < 7; i++)
                lds128(vb01 + base + (i << 4), a0[i], a1[i]);

            u64 muxy[2], S[2];
            #pragma unroll
            for (int o = 0; o < 2; o++) {
                u64 mx = hconv(a0 + o, wA, wB);
                u64 my = hconv(a1 + o, wA, wB);
                muxy[o] = mul2(mx, my);
                S[o]    = fma2(mx, mx, mul2(my, my));
            }

            #pragma unroll
            for (int i = 0; i < 7; i++)
                lds128(vb23 + base + (i << 4), a0[i], a1[i]);

            float part = 0.f;
            #pragma unroll
            for (int o = 0; o < 2; o++) {
                u64 m2 = hconv(a0 + o, wA, wB);
                u64 m3 = hconv(a1 + o, wA, wB);
                u64 B1 = add2(S[o], c1_2);
                u64 B2 = fma2(n1_2, S[o], add2(m2, c2_2));
                u64 A1 = fma2(two_2, muxy[o], c1_2);
                u64 A2 = fma2(two_2, fma2(n1_2, muxy[o], m3), c2_2);
                u64 num = mul2(A1, A2);
                u64 den = fma2(B1, B2, eps2);
                float nl, nh, dl, dh;
                unpack2(num, nl, nh);
                unpack2(den, dl, dh);
                part += __fdividef(nl, dl) + __fdividef(nh, dh);
            }
            if (ty * TH + r < IMG_H) lsum += part;   // partial-tile guard
        }
    }

    // ---- Block reduction (8 warps) ----
    #pragma unroll
    for (int off = 16; off > 0; off >>= 1)
        lsum += __shfl_down_sync(0xFFFFFFFFu, lsum, off);

    __syncthreads();
    float* red = smem;
    int warp = tid >> 5, lane = tid & 31;
    if (lane == 0) red[warp] = lsum;
    __syncthreads();
    if (warp == 0) {
        float v = (lane < (THREADS / 32)) ? red[lane] : 0.f;
        #pragma unroll
        for (int off = 4; off > 0; off >>= 1)
            v += __shfl_down_sync(0xFFFFFFFFu, v, off);
        if (lane == 0)
            atomicAdd(&g_slots[(blockIdx.x & (NSLOTS - 1)) * SLOT_STRIDE],
                      (double)v);
    }
}

extern "C" void kernel_launch(void* const* d_in, const int* in_sizes, int n_in,
                              void* d_out, int out_size) {
    (void)in_sizes; (void)n_in; (void)out_size;
    const float* x = (const float*)d_in[0];
    const float* y = (const float*)d_in[1];
    float* out = (float*)d_out;

    static bool attr_set = false;
    if (!attr_set) {
        cudaFuncSetAttribute(ssim_main_k,
                             cudaFuncAttributeMaxDynamicSharedMemorySize,
                             SMEM_BYTES);
        attr_set = true;
    }

    ssim_main_k<<<NBLOCKS, THREADS, SMEM_BYTES>>>(x, y);
    ssim_finalize_k<<<1, 32>>>(out);
    ssim_zero_k<<<1, NSLOTS>>>();
}

// round 8
// speedup vs baseline: 1.0062x; 1.0062x over previous
#include <cuda_runtime.h>

// SSIM loss, fused separable 11x11 Gaussian, B=64, H=W=512.
// R8: TH=32 / 3 CTAs (best tiling) + XOR-swizzled v region -> conflict-free
//     stage-B stores and stage-C window reads; 4-pair stage-C units (window 9,
//     2.25 LDS.128 per pixel); plane-pair 16B v units (v01 | v23).

#define BATCH 64
#define IMG_H 512
#define IMG_W 512
#define TH 32
#define HALO 5
#define PH 42                 // TH + 10
#define NCP 38                // padded col-pairs (76 cols incl. 2 pad)
#define THREADS 256
#define NBLOCKS (BATCH * 128) // 8x16 tiles per image

#define IN_BYTES  (PH * NCP * 16)        // 25536
#define V_BYTES   (TH * NCP * 32)        // 38912 (4 planes, 32B per col-pair)
#define SMEM_BYTES (IN_BYTES + V_BYTES)  // 64448 -> 3 CTAs/SM

#define NSLOTS 32
#define SLOT_STRIDE 16

typedef unsigned long long u64;

// Gaussian(ks=11, sigma=1.5), normalized.
#define W0 0.00102838f
#define W1 0.00759876f
#define W2 0.03600077f
#define W3 0.10936069f
#define W4 0.21300553f
#define W5 0.26601172f
__device__ __constant__ float c_w[11] = {W0,W1,W2,W3,W4,W5,W4,W3,W2,W1,W0};

__device__ double g_slots[NSLOTS * SLOT_STRIDE];   // static zero-init

__device__ __forceinline__ unsigned smem_u32(const void* p) {
    unsigned r;
    asm("{ .reg .u64 t; cvta.to.shared.u64 t, %1; cvt.u32.u64 %0, t; }"
        : "=r"(r) : "l"(p));
    return r;
}
// Fold byte-address bits [7:9] into [4:6]: de-conflicts 32B-stride writes and
// 128B-stride window reads simultaneously. Involution; used for ALL v accesses.
__device__ __forceinline__ unsigned swz(unsigned a) {
    return a ^ ((a >> 3) & 0x70u);
}
__device__ __forceinline__ u64 pack2(float lo, float hi) {
    u64 r; asm("mov.b64 %0, {%1,%2};" : "=l"(r) : "f"(lo), "f"(hi)); return r;
}
__device__ __forceinline__ void unpack2(u64 v, float& a, float& b) {
    asm("mov.b64 {%0,%1}, %2;" : "=f"(a), "=f"(b) : "l"(v));
}
__device__ __forceinline__ u64 swap2(u64 v) {
    u64 r;
    asm("{ .reg .b32 lo, hi; mov.b64 {lo,hi}, %1; mov.b64 %0, {hi,lo}; }"
        : "=l"(r) : "l"(v));
    return r;
}
__device__ __forceinline__ u64 fma2(u64 a, u64 b, u64 c) {
    u64 d; asm("fma.rn.f32x2 %0, %1, %2, %3;" : "=l"(d) : "l"(a), "l"(b), "l"(c));
    return d;
}
__device__ __forceinline__ u64 mul2(u64 a, u64 b) {
    u64 d; asm("mul.rn.f32x2 %0, %1, %2;" : "=l"(d) : "l"(a), "l"(b)); return d;
}
__device__ __forceinline__ u64 add2(u64 a, u64 b) {
    u64 d; asm("add.rn.f32x2 %0, %1, %2;" : "=l"(d) : "l"(a), "l"(b)); return d;
}
__device__ __forceinline__ void lds128(unsigned addr, u64& a, u64& b) {
    asm volatile("ld.shared.v2.b64 {%0,%1}, [%2];" : "=l"(a), "=l"(b) : "r"(addr));
}
__device__ __forceinline__ void sts128(unsigned addr, u64 a, u64 b) {
    asm volatile("st.shared.v2.b64 [%0], {%1,%2};" :: "r"(addr), "l"(a), "l"(b));
}

__global__ void ssim_zero_k() {
    g_slots[threadIdx.x * SLOT_STRIDE] = 0.0;
}

__global__ void ssim_finalize_k(float* out) {
    int t = threadIdx.x;
    double v = g_slots[t * SLOT_STRIDE];
    #pragma unroll
    for (int off = 16; off > 0; off >>= 1)
        v += __shfl_down_sync(0xFFFFFFFFu, v, off);
    if (t == 0)
        out[0] = (float)(1.0 - v / ((double)BATCH * IMG_H * IMG_W));
}

// 11-tap horizontal conv on packed pairs via even/odd accumulators.
__device__ __forceinline__ u64 hconv(const u64* win, const u64* wA, const u64* wB) {
    u64 acc = 0, accS = 0;
    #pragma unroll
    for (int i = 0; i < 6; i++) {
        acc  = fma2(wA[i], win[i], acc);
        accS = fma2(wB[i], win[i], accS);
    }
    return add2(acc, swap2(accS));
}

__global__ __launch_bounds__(THREADS, 3)
void ssim_main_k(const float* __restrict__ x, const float* __restrict__ y) {
    extern __shared__ float smem[];
    const unsigned sb = smem_u32(smem);
    const unsigned vb = sb + IN_BYTES;

    const int tid = threadIdx.x;
    const int blk = blockIdx.x;
    const int b  = blk >> 7;
    const int t  = blk & 127;
    const int ty = t >> 3;
    const int tx = t & 7;
    const int gx0 = tx * 64 - HALO;
    const int gy0 = ty * TH - HALO;

    const float* __restrict__ xb = x + (size_t)b * IMG_H * IMG_W;
    const float* __restrict__ yb = y + (size_t)b * IMG_H * IMG_W;

    // ---- Stage A: halo load into interleaved tile (x0,x1,y0,y1), linear ----
    {
        int r  = tid / NCP;
        int cp = tid - r * NCP;
        const bool interior = (gx0 >= 0) & (gy0 >= 0) &
                              (gx0 + 2 * NCP <= IMG_W) & (gy0 + PH <= IMG_H);
        if (interior) {
            const float* __restrict__ xr = xb + (size_t)gy0 * IMG_W + gx0;
            const float* __restrict__ yr = yb + (size_t)gy0 * IMG_W + gx0;
            for (int e = tid; e < PH * NCP; e += THREADS) {
                int off = r * IMG_W + 2 * cp;
                sts128(sb + (unsigned)(e << 4),
                       pack2(xr[off], xr[off + 1]),
                       pack2(yr[off], yr[off + 1]));
                r += 6; cp += (THREADS - 6 * NCP);
                if (cp >= NCP) { cp -= NCP; r += 1; }
            }
        } else {
            for (int e = tid; e < PH * NCP; e += THREADS) {
                int gy = gy0 + r;
                int g0 = gx0 + 2 * cp;
                float x0 = 0.f, x1 = 0.f, y0 = 0.f, y1 = 0.f;
                if ((unsigned)gy < IMG_H) {
                    size_t rowb = (size_t)gy * IMG_W;
                    if ((unsigned)g0 < IMG_W) { x0 = xb[rowb + g0]; y0 = yb[rowb + g0]; }
                    if ((unsigned)(g0 + 1) < IMG_W) { x1 = xb[rowb + g0 + 1]; y1 = yb[rowb + g0 + 1]; }
                }
                sts128(sb + (unsigned)(e << 4), pack2(x0, x1), pack2(y0, y1));
                r += 6; cp += (THREADS - 6 * NCP);
                if (cp >= NCP) { cp -= NCP; r += 1; }
            }
        }
    }
    __syncthreads();

    // ---- Stage B: vertical conv {x, y, x2+y2, xy}, 4-row strips, 304 items ----
    {
        u64 w2[6];   // symmetric: w[k] == w[10-k]
        #pragma unroll
        for (int k = 0; k < 6; k++) w2[k] = pack2(c_w[k], c_w[k]);

        for (int e = tid; e < 8 * NCP; e += THREADS) {
            int rs = e / NCP;
            int cp = e - rs * NCP;
            int r0 = rs * 4;
            unsigned in0 = sb + (unsigned)((r0 * NCP + cp) << 4);

            u64 s0[4] = {0,0,0,0};
            u64 s1[4] = {0,0,0,0};
            u64 s2[4] = {0,0,0,0};
            u64 s3[4] = {0,0,0,0};
            #pragma unroll
            for (int j = 0; j < 14; j++) {
                u64 a, bb;
                lds128(in0 + j * (NCP * 16), a, bb);
                u64 ab = mul2(a, bb);
                u64 qq = fma2(a, a, mul2(bb, bb));
                #pragma unroll
                for (int tt = 0; tt < 4; tt++) {
                    int k = j - tt;
                    if (k >= 0 && k <= 10) {
                        u64 wk = w2[(k <= 5) ? k : 10 - k];
                        s0[tt] = fma2(wk, a,  s0[tt]);
                        s1[tt] = fma2(wk, bb, s1[tt]);
                        s2[tt] = fma2(wk, qq, s2[tt]);
                        s3[tt] = fma2(wk, ab, s3[tt]);
                    }
                }
            }
            #pragma unroll
            for (int tt = 0; tt < 4; tt++) {
                unsigned u = (unsigned)(((r0 + tt) * NCP + cp) << 5);
                sts128(vb + swz(u),      s0[tt], s1[tt]);   // v01
                sts128(vb + swz(u + 16), s2[tt], s3[tt]);   // v23
            }
        }
    }
    __syncthreads();

    // ---- Stage C: horizontal conv + SSIM; 256 units = 32 rows x 8 qblocks ----
    float lsum = 0.f;
    {
        u64 wA[6], wB[6];
        #pragma unroll
        for (int i = 0; i < 6; i++) {
            wA[i] = pack2(c_w[2 * i], c_w[2 * i]);
            float blo = (i >= 1) ? c_w[2 * i - 1] : 0.f;
            float bhi = (i <= 4) ? c_w[2 * i + 1] : 0.f;
            wB[i] = pack2(blo, bhi);
        }
        const u64 c1_2  = pack2(1e-4f, 1e-4f);
        const u64 c2_2  = pack2(9e-4f, 9e-4f);
        const u64 eps2  = pack2(1e-12f, 1e-12f);
        const u64 n1_2  = pack2(-1.f, -1.f);
        const u64 two_2 = pack2(2.f, 2.f);

        const int r  = tid >> 3;        // 0..31
        const int q0 = (tid & 7) * 4;   // 4 output pairs per unit

        u64 pa[9], pb[9];
        // pass 1: v01 window -> mu_x, mu_y
        #pragma unroll
        for (int i = 0; i < 9; i++) {
            unsigned u = (unsigned)((r * NCP + q0 + i) << 5);
            lds128(vb + swz(u), pa[i], pb[i]);
        }
        u64 muxy[4], S[4];
        #pragma unroll
        for (int qq = 0; qq < 4; qq++) {
            u64 mx = hconv(pa + qq, wA, wB);
            u64 my = hconv(pb + qq, wA, wB);
            muxy[qq] = mul2(mx, my);
            S[qq]    = fma2(mx, mx, mul2(my, my));
        }
        // pass 2: v23 window -> conv(x2+y2), conv(xy); then SSIM
        #pragma unroll
        for (int i = 0; i < 9; i++) {
            unsigned u = (unsigned)((r * NCP + q0 + i) << 5);
            lds128(vb + swz(u + 16), pa[i], pb[i]);
        }
        #pragma unroll
        for (int qq = 0; qq < 4; qq++) {
            u64 m2 = hconv(pa + qq, wA, wB);
            u64 m3 = hconv(pb + qq, wA, wB);
            u64 B1 = add2(S[qq], c1_2);
            u64 B2 = fma2(n1_2, S[qq], add2(m2, c2_2));
            u64 A1 = fma2(two_2, muxy[qq], c1_2);
            u64 A2 = fma2(two_2, fma2(n1_2, muxy[qq], m3), c2_2);
            u64 num = mul2(A1, A2);
            u64 den = fma2(B1, B2, eps2);
            float nl, nh, dl, dh;
            unpack2(num, nl, nh);
            unpack2(den, dl, dh);
            lsum += __fdividef(nl, dl) + __fdividef(nh, dh);
        }
    }

    // ---- Block reduction (8 warps) ----
    #pragma unroll
    for (int off = 16; off > 0; off >>= 1)
        lsum += __shfl_down_sync(0xFFFFFFFFu, lsum, off);

    __syncthreads();
    float* red = smem;
    int warp = tid >> 5, lane = tid & 31;
    if (lane == 0) red[warp] = lsum;
    __syncthreads();
    if (warp == 0) {
        float v = (lane < (THREADS / 32)) ? red[lane] : 0.f;
        #pragma unroll
        for (int off = 4; off > 0; off >>= 1)
            v += __shfl_down_sync(0xFFFFFFFFu, v, off);
        if (lane == 0)
            atomicAdd(&g_slots[(blockIdx.x & (NSLOTS - 1)) * SLOT_STRIDE],
                      (double)v);
    }
}

extern "C" void kernel_launch(void* const* d_in, const int* in_sizes, int n_in,
                              void* d_out, int out_size) {
    (void)in_sizes; (void)n_in; (void)out_size;
    const float* x = (const float*)d_in[0];
    const float* y = (const float*)d_in[1];
    float* out = (float*)d_out;

    static bool attr_set = false;
    if (!attr_set) {
        cudaFuncSetAttribute(ssim_main_k,
                             cudaFuncAttributeMaxDynamicSharedMemorySize,
                             SMEM_BYTES);
        attr_set = true;
    }

    ssim_main_k<<<NBLOCKS, THREADS, SMEM_BYTES>>>(x, y);
    ssim_finalize_k<<<1, 32>>>(out);
    ssim_zero_k<<<1, NSLOTS>>>();
}

// round 10
// speedup vs baseline: 1.0901x; 1.0833x over previous
#include <cuda_runtime.h>

// SSIM loss, fused separable 11x11 Gaussian, B=64, H=W=512.
// R10: R9 design with the swizzle-offset bug fixed: v23 address is
//      swz(u + 16) == swz(u) ^ 16  (XOR, never ADD — swz carries corrupt bits).
//      TH=24, 4 CTAs/SM, conflict-free swizzled v01/v23 layout.

#define BATCH 64
#define IMG_H 512
#define IMG_W 512
#define TH 24
#define HALO 5
#define PH 34                 // TH + 10
#define NCP 38                // padded col-pairs (76 cols incl. 2 pad)
#define THREADS 256
#define TILES_X 8
#define TILES_Y 22
#define NBLOCKS (BATCH * TILES_X * TILES_Y)   // 11264

#define IN_BYTES  (PH * NCP * 16)        // 20672
#define V_BYTES   (TH * NCP * 32)        // 29184
#define SMEM_BYTES (IN_BYTES + V_BYTES)  // 49856 -> 4 CTAs/SM

#define NSLOTS 32
#define SLOT_STRIDE 16

typedef unsigned long long u64;

// Gaussian(ks=11, sigma=1.5), normalized.
#define W0 0.00102838f
#define W1 0.00759876f
#define W2 0.03600077f
#define W3 0.10936069f
#define W4 0.21300553f
#define W5 0.26601172f
__device__ __constant__ float c_w[11] = {W0,W1,W2,W3,W4,W5,W4,W3,W2,W1,W0};

__device__ double g_slots[NSLOTS * SLOT_STRIDE];   // static zero-init

__device__ __forceinline__ unsigned smem_u32(const void* p) {
    unsigned r;
    asm("{ .reg .u64 t; cvta.to.shared.u64 t, %1; cvt.u32.u64 %0, t; }"
        : "=r"(r) : "l"(p));
    return r;
}
// Fold byte-address bits [7:9] into [4:6]; conflict-free for 32B-stride
// stores (stage B) and 32B-unit window reads (stage C). Involution.
// NOTE: apply to the FULL offset including the +16 v23 sub-offset.
__device__ __forceinline__ unsigned swz(unsigned a) {
    return a ^ ((a >> 3) & 0x70u);
}
__device__ __forceinline__ u64 pack2(float lo, float hi) {
    u64 r; asm("mov.b64 %0, {%1,%2};" : "=l"(r) : "f"(lo), "f"(hi)); return r;
}
__device__ __forceinline__ void unpack2(u64 v, float& a, float& b) {
    asm("mov.b64 {%0,%1}, %2;" : "=f"(a), "=f"(b) : "l"(v));
}
__device__ __forceinline__ u64 swap2(u64 v) {
    u64 r;
    asm("{ .reg .b32 lo, hi; mov.b64 {lo,hi}, %1; mov.b64 %0, {hi,lo}; }"
        : "=l"(r) : "l"(v));
    return r;
}
__device__ __forceinline__ u64 fma2(u64 a, u64 b, u64 c) {
    u64 d; asm("fma.rn.f32x2 %0, %1, %2, %3;" : "=l"(d) : "l"(a), "l"(b), "l"(c));
    return d;
}
__device__ __forceinline__ u64 mul2(u64 a, u64 b) {
    u64 d; asm("mul.rn.f32x2 %0, %1, %2;" : "=l"(d) : "l"(a), "l"(b)); return d;
}
__device__ __forceinline__ u64 add2(u64 a, u64 b) {
    u64 d; asm("add.rn.f32x2 %0, %1, %2;" : "=l"(d) : "l"(a), "l"(b)); return d;
}
__device__ __forceinline__ void lds128(unsigned addr, u64& a, u64& b) {
    asm volatile("ld.shared.v2.b64 {%0,%1}, [%2];" : "=l"(a), "=l"(b) : "r"(addr));
}
__device__ __forceinline__ void sts128(unsigned addr, u64 a, u64 b) {
    asm volatile("st.shared.v2.b64 [%0], {%1,%2};" :: "r"(addr), "l"(a), "l"(b));
}

__global__ void ssim_zero_k() {
    g_slots[threadIdx.x * SLOT_STRIDE] = 0.0;
}

__global__ void ssim_finalize_k(float* out) {
    int t = threadIdx.x;
    double v = g_slots[t * SLOT_STRIDE];
    #pragma unroll
    for (int off = 16; off > 0; off >>= 1)
        v += __shfl_down_sync(0xFFFFFFFFu, v, off);
    if (t == 0)
        out[0] = (float)(1.0 - v / ((double)BATCH * IMG_H * IMG_W));
}

// 11-tap horizontal conv on packed pairs via even/odd accumulators.
__device__ __forceinline__ u64 hconv(const u64* win, const u64* wA, const u64* wB) {
    u64 acc = 0, accS = 0;
    #pragma unroll
    for (int i = 0; i < 6; i++) {
        acc  = fma2(wA[i], win[i], acc);
        accS = fma2(wB[i], win[i], accS);
    }
    return add2(acc, swap2(accS));
}

__global__ __launch_bounds__(THREADS, 4)
void ssim_main_k(const float* __restrict__ x, const float* __restrict__ y) {
    extern __shared__ float smem[];
    const unsigned sb = smem_u32(smem);
    const unsigned vb = sb + IN_BYTES;

    const int tid = threadIdx.x;
    const int blk = blockIdx.x;
    const int b  = blk / (TILES_X * TILES_Y);
    const int t  = blk - b * (TILES_X * TILES_Y);
    const int ty = t >> 3;
    const int tx = t & 7;
    const int gx0 = tx * 64 - HALO;
    const int gy0 = ty * TH - HALO;

    const float* __restrict__ xb = x + (size_t)b * IMG_H * IMG_W;
    const float* __restrict__ yb = y + (size_t)b * IMG_H * IMG_W;

    // ---- Stage A: halo load into interleaved tile (x0,x1,y0,y1) ----
    {
        int r  = tid / NCP;
        int cp = tid - r * NCP;
        const bool interior = (gx0 >= 0) & (gy0 >= 0) &
                              (gx0 + 2 * NCP <= IMG_W) & (gy0 + PH <= IMG_H);
        if (interior) {
            const float* __restrict__ xr = xb + (size_t)gy0 * IMG_W + gx0;
            const float* __restrict__ yr = yb + (size_t)gy0 * IMG_W + gx0;
            for (int e = tid; e < PH * NCP; e += THREADS) {
                int off = r * IMG_W + 2 * cp;
                sts128(sb + (unsigned)(e << 4),
                       pack2(xr[off], xr[off + 1]),
                       pack2(yr[off], yr[off + 1]));
                r += 6; cp += (THREADS - 6 * NCP);
                if (cp >= NCP) { cp -= NCP; r += 1; }
            }
        } else {
            for (int e = tid; e < PH * NCP; e += THREADS) {
                int gy = gy0 + r;
                int g0 = gx0 + 2 * cp;
                float x0 = 0.f, x1 = 0.f, y0 = 0.f, y1 = 0.f;
                if ((unsigned)gy < IMG_H) {
                    size_t rowb = (size_t)gy * IMG_W;
                    if ((unsigned)g0 < IMG_W) { x0 = xb[rowb + g0]; y0 = yb[rowb + g0]; }
                    if ((unsigned)(g0 + 1) < IMG_W) { x1 = xb[rowb + g0 + 1]; y1 = yb[rowb + g0 + 1]; }
                }
                sts128(sb + (unsigned)(e << 4), pack2(x0, x1), pack2(y0, y1));
                r += 6; cp += (THREADS - 6 * NCP);
                if (cp >= NCP) { cp -= NCP; r += 1; }
            }
        }
    }
    __syncthreads();

    // ---- Stage B: vertical conv {x, y, x2+y2, xy}, 4-row strips, 228 items ----
    if (tid < 6 * NCP) {
        u64 w2[6];   // symmetric: w[k] == w[10-k]
        #pragma unroll
        for (int k = 0; k < 6; k++) w2[k] = pack2(c_w[k], c_w[k]);

        int rs = tid / NCP;
        int cp = tid - rs * NCP;
        int r0 = rs * 4;
        unsigned in0 = sb + (unsigned)((r0 * NCP + cp) << 4);

        u64 s0[4] = {0,0,0,0};
        u64 s1[4] = {0,0,0,0};
        u64 s2[4] = {0,0,0,0};
        u64 s3[4] = {0,0,0,0};
        #pragma unroll
        for (int j = 0; j < 14; j++) {
            u64 a, bb;
            lds128(in0 + j * (NCP * 16), a, bb);
            u64 ab = mul2(a, bb);
            u64 qq = fma2(a, a, mul2(bb, bb));
            #pragma unroll
            for (int tt = 0; tt < 4; tt++) {
                int k = j - tt;
                if (k >= 0 && k <= 10) {
                    u64 wk = w2[(k <= 5) ? k : 10 - k];
                    s0[tt] = fma2(wk, a,  s0[tt]);
                    s1[tt] = fma2(wk, bb, s1[tt]);
                    s2[tt] = fma2(wk, qq, s2[tt]);
                    s3[tt] = fma2(wk, ab, s3[tt]);
                }
            }
        }
        #pragma unroll
        for (int tt = 0; tt < 4; tt++) {
            unsigned u = (unsigned)(((r0 + tt) * NCP + cp) << 5);
            unsigned su = vb + swz(u);
            sts128(su,        s0[tt], s1[tt]);   // v01 at swz(u)
            sts128(su ^ 16u,  s2[tt], s3[tt]);   // v23 at swz(u+16) == swz(u)^16
        }
    }
    __syncthreads();

    // ---- Stage C: horizontal conv + SSIM; 384 units = 24 rows x 16 qblocks ----
    float lsum = 0.f;
    {
        u64 wA[6], wB[6];
        #pragma unroll
        for (int i = 0; i < 6; i++) {
            wA[i] = pack2(c_w[2 * i], c_w[2 * i]);
            float blo = (i >= 1) ? c_w[2 * i - 1] : 0.f;
            float bhi = (i <= 4) ? c_w[2 * i + 1] : 0.f;
            wB[i] = pack2(blo, bhi);
        }
        const u64 c1_2  = pack2(1e-4f, 1e-4f);
        const u64 c2_2  = pack2(9e-4f, 9e-4f);
        const u64 eps2  = pack2(1e-12f, 1e-12f);
        const u64 n1_2  = pack2(-1.f, -1.f);
        const u64 two_2 = pack2(2.f, 2.f);

        for (int e = tid; e < 24 * 16; e += THREADS) {
            int r  = e >> 4;
            int qb = e & 15;                 // 2 output pairs per unit
            unsigned ub = (unsigned)((r * NCP + 2 * qb) << 5);

            u64 pa[7], pb[7];
            // pass 1: v01 window -> mu_x, mu_y
            #pragma unroll
            for (int i = 0; i < 7; i++)
                lds128(vb + swz(ub + (unsigned)(i << 5)), pa[i], pb[i]);

            u64 muxy[2], S[2];
            #pragma unroll
            for (int o = 0; o < 2; o++) {
                u64 mx = hconv(pa + o, wA, wB);
                u64 my = hconv(pb + o, wA, wB);
                muxy[o] = mul2(mx, my);
                S[o]    = fma2(mx, mx, mul2(my, my));
            }

            // pass 2: v23 window (sub-offset swizzled via XOR)
            #pragma unroll
            for (int i = 0; i < 7; i++)
                lds128(vb + (swz(ub + (unsigned)(i << 5)) ^ 16u), pa[i], pb[i]);

            float part = 0.f;
            #pragma unroll
            for (int o = 0; o < 2; o++) {
                u64 m2 = hconv(pa + o, wA, wB);
                u64 m3 = hconv(pb + o, wA, wB);
                u64 B1 = add2(S[o], c1_2);
                u64 B2 = fma2(n1_2, S[o], add2(m2, c2_2));
                u64 A1 = fma2(two_2, muxy[o], c1_2);
                u64 A2 = fma2(two_2, fma2(n1_2, muxy[o], m3), c2_2);
                u64 num = mul2(A1, A2);
                u64 den = fma2(B1, B2, eps2);
                float nl, nh, dl, dh;
                unpack2(num, nl, nh);
                unpack2(den, dl, dh);
                part += __fdividef(nl, dl) + __fdividef(nh, dh);
            }
            if (ty * TH + r < IMG_H) lsum += part;   // partial-tile guard
        }
    }

    // ---- Block reduction (8 warps) ----
    #pragma unroll
    for (int off = 16; off > 0; off >>= 1)
        lsum += __shfl_down_sync(0xFFFFFFFFu, lsum, off);

    __syncthreads();
    float* red = smem;
    int warp = tid >> 5, lane = tid & 31;
    if (lane == 0) red[warp] = lsum;
    __syncthreads();
    if (warp == 0) {
        float v = (lane < (THREADS / 32)) ? red[lane] : 0.f;
        #pragma unroll
        for (int off = 4; off > 0; off >>= 1)
            v += __shfl_down_sync(0xFFFFFFFFu, v, off);
        if (lane == 0)
            atomicAdd(&g_slots[(blockIdx.x & (NSLOTS - 1)) * SLOT_STRIDE],
                      (double)v);
    }
}

extern "C" void kernel_launch(void* const* d_in, const int* in_sizes, int n_in,
                              void* d_out, int out_size) {
    (void)in_sizes; (void)n_in; (void)out_size;
    const float* x = (const float*)d_in[0];
    const float* y = (const float*)d_in[1];
    float* out = (float*)d_out;

    static bool attr_set = false;
    if (!attr_set) {
        cudaFuncSetAttribute(ssim_main_k,
                             cudaFuncAttributeMaxDynamicSharedMemorySize,
                             SMEM_BYTES);
        attr_set = true;
    }

    ssim_main_k<<<NBLOCKS, THREADS, SMEM_BYTES>>>(x, y);
    ssim_finalize_k<<<1, 32>>>(out);
    ssim_zero_k<<<1, NSLOTS>>>();
}

// round 11
// speedup vs baseline: 1.2848x; 1.1786x over previous
#include <cuda_runtime.h>

// SSIM loss, fused separable 11x11 Gaussian, B=64, H=W=512.
// R11: stage A deleted. Even-aligned column pairs (gx0 = 64*tx - 6) make the
//      stage-B GMEM loads 8B-aligned ld.global.nc.b64 (coalesced), so the
//      input smem tile + its realignment pass are gone (-41KB L1 traffic/tile,
//      -1 barrier). Stage C window becomes 8 units with re-derived even/odd
//      weight vectors (wS splat, wD staggered). smem = v region only (29.2KB),
//      4 CTAs/SM.

#define BATCH 64
#define IMG_H 512
#define IMG_W 512
#define TH 24
#define HALO 5
#define NCP 38                // pairs per padded row (cols 64*tx-6 .. 64*tx+69)
#define THREADS 256
#define TILES_X 8
#define TILES_Y 22
#define NBLOCKS (BATCH * TILES_X * TILES_Y)   // 11264

#define V_BYTES   (TH * NCP * 32)    // 29184
#define SMEM_BYTES V_BYTES           // -> 4 CTAs/SM (reg-limited)

#define NSLOTS 32
#define SLOT_STRIDE 16

typedef unsigned long long u64;

// Gaussian(ks=11, sigma=1.5), normalized.
#define W0 0.00102838f
#define W1 0.00759876f
#define W2 0.03600077f
#define W3 0.10936069f
#define W4 0.21300553f
#define W5 0.26601172f
__device__ __constant__ float c_w[11] = {W0,W1,W2,W3,W4,W5,W4,W3,W2,W1,W0};

__device__ double g_slots[NSLOTS * SLOT_STRIDE];   // static zero-init

__device__ __forceinline__ unsigned smem_u32(const void* p) {
    unsigned r;
    asm("{ .reg .u64 t; cvta.to.shared.u64 t, %1; cvt.u32.u64 %0, t; }"
        : "=r"(r) : "l"(p));
    return r;
}
// Fold byte-address bits [7:9] into [4:6]; conflict-free for 32B-stride
// stores (stage B) and 32B-unit window reads (stage C). Involution.
// Sub-offsets within a 32B unit are applied via XOR (swz(u+16)==swz(u)^16).
__device__ __forceinline__ unsigned swz(unsigned a) {
    return a ^ ((a >> 3) & 0x70u);
}
__device__ __forceinline__ u64 pack2(float lo, float hi) {
    u64 r; asm("mov.b64 %0, {%1,%2};" : "=l"(r) : "f"(lo), "f"(hi)); return r;
}
__device__ __forceinline__ void unpack2(u64 v, float& a, float& b) {
    asm("mov.b64 {%0,%1}, %2;" : "=f"(a), "=f"(b) : "l"(v));
}
__device__ __forceinline__ u64 swap2(u64 v) {
    u64 r;
    asm("{ .reg .b32 lo, hi; mov.b64 {lo,hi}, %1; mov.b64 %0, {hi,lo}; }"
        : "=l"(r) : "l"(v));
    return r;
}
__device__ __forceinline__ u64 fma2(u64 a, u64 b, u64 c) {
    u64 d; asm("fma.rn.f32x2 %0, %1, %2, %3;" : "=l"(d) : "l"(a), "l"(b), "l"(c));
    return d;
}
__device__ __forceinline__ u64 mul2(u64 a, u64 b) {
    u64 d; asm("mul.rn.f32x2 %0, %1, %2;" : "=l"(d) : "l"(a), "l"(b)); return d;
}
__device__ __forceinline__ u64 add2(u64 a, u64 b) {
    u64 d; asm("add.rn.f32x2 %0, %1, %2;" : "=l"(d) : "l"(a), "l"(b)); return d;
}
__device__ __forceinline__ u64 ldg64(const float* p) {
    u64 r; asm volatile("ld.global.nc.b64 %0, [%1];" : "=l"(r) : "l"(p));
    return r;
}
__device__ __forceinline__ void lds128(unsigned addr, u64& a, u64& b) {
    asm volatile("ld.shared.v2.b64 {%0,%1}, [%2];" : "=l"(a), "=l"(b) : "r"(addr));
}
__device__ __forceinline__ void sts128(unsigned addr, u64 a, u64 b) {
    asm volatile("st.shared.v2.b64 [%0], {%1,%2};" :: "r"(addr), "l"(a), "l"(b));
}

__global__ void ssim_zero_k() {
    g_slots[threadIdx.x * SLOT_STRIDE] = 0.0;
}

__global__ void ssim_finalize_k(float* out) {
    int t = threadIdx.x;
    double v = g_slots[t * SLOT_STRIDE];
    #pragma unroll
    for (int off = 16; off > 0; off >>= 1)
        v += __shfl_down_sync(0xFFFFFFFFu, v, off);
    if (t == 0)
        out[0] = (float)(1.0 - v / ((double)BATCH * IMG_H * IMG_W));
}

// Horizontal 11-tap conv, EVEN-aligned pairs. Window win[0..6] = pairs q..q+6
// for output pair q (tile-local outputs at window entry index 3).
// Derivation (verified tap-by-tap):
//   out.lo = sum_k w_k in[2q+1+k],  out.hi = sum_k w_k in[2q+2+k]
//   ACC  = sum_{i=1..5} splat(w[2i-1]) * win[i]           (odd taps)
//   ACCS = (0,w0)*win[0] + sum_{i=1..5}(w[2i-2],w[2i])*win[i] + (w10,0)*win[6]
//   out  = ACC + swap(ACCS)
__device__ __forceinline__ u64 hconv_e(const u64* win, const u64* wS, const u64* wD) {
    u64 acc = 0, accS = 0;
    #pragma unroll
    for (int i = 1; i <= 5; i++) {
        acc  = fma2(wS[i - 1], win[i], acc);
        accS = fma2(wD[i],     win[i], accS);
    }
    accS = fma2(wD[0], win[0], accS);
    accS = fma2(wD[6], win[6], accS);
    return add2(acc, swap2(accS));
}

__global__ __launch_bounds__(THREADS, 4)
void ssim_main_k(const float* __restrict__ x, const float* __restrict__ y) {
    extern __shared__ float smem[];
    const unsigned vb = smem_u32(smem);

    const int tid = threadIdx.x;
    const int blk = blockIdx.x;
    const int b  = blk / (TILES_X * TILES_Y);
    const int t  = blk - b * (TILES_X * TILES_Y);
    const int ty = t >> 3;
    const int tx = t & 7;
    const int gx0 = tx * 64 - 6;          // EVEN left edge (covers halo -5)
    const int gy0 = ty * TH - HALO;

    const float* __restrict__ xb = x + (size_t)b * IMG_H * IMG_W;
    const float* __restrict__ yb = y + (size_t)b * IMG_H * IMG_W;

    // ---- Stage B: vertical conv {x, y, x2+y2, xy} straight from GMEM.
    //      228 items = 6 strips x 38 col-pairs, 4-row strips, 14 rows each.
    if (tid < 6 * NCP) {
        u64 w2[6];   // symmetric: w[k] == w[10-k]
        #pragma unroll
        for (int k = 0; k < 6; k++) w2[k] = pack2(c_w[k], c_w[k]);

        int rs = tid / NCP;
        int cp = tid - rs * NCP;
        int r0 = rs * 4;

        u64 s0[4] = {0,0,0,0};
        u64 s1[4] = {0,0,0,0};
        u64 s2[4] = {0,0,0,0};
        u64 s3[4] = {0,0,0,0};

        const bool interior = (gx0 >= 0) & (gx0 + 2 * NCP <= IMG_W) &
                              (gy0 >= 0) & (gy0 + TH + 10 <= IMG_H);
        if (interior) {
            const float* xp = xb + (size_t)(gy0 + r0) * IMG_W + (gx0 + 2 * cp);
            const float* yp = yb + (size_t)(gy0 + r0) * IMG_W + (gx0 + 2 * cp);
            #pragma unroll
            for (int j = 0; j < 14; j++) {
                u64 a  = ldg64(xp + j * IMG_W);
                u64 bb = ldg64(yp + j * IMG_W);
                u64 ab = mul2(a, bb);
                u64 qq = fma2(a, a, mul2(bb, bb));
                #pragma unroll
                for (int tt = 0; tt < 4; tt++) {
                    int k = j - tt;
                    if (k >= 0 && k <= 10) {
                        u64 wk = w2[(k <= 5) ? k : 10 - k];
                        s0[tt] = fma2(wk, a,  s0[tt]);
                        s1[tt] = fma2(wk, bb, s1[tt]);
                        s2[tt] = fma2(wk, qq, s2[tt]);
                        s3[tt] = fma2(wk, ab, s3[tt]);
                    }
                }
            }
        } else {
            int c0 = gx0 + 2 * cp;
            #pragma unroll
            for (int j = 0; j < 14; j++) {
                int gy = gy0 + r0 + j;
                float x0 = 0.f, x1 = 0.f, y0 = 0.f, y1 = 0.f;
                if ((unsigned)gy < IMG_H) {
                    size_t rowb = (size_t)gy * IMG_W;
                    if ((unsigned)c0 < IMG_W) { x0 = xb[rowb + c0]; y0 = yb[rowb + c0]; }
                    if ((unsigned)(c0 + 1) < IMG_W) { x1 = xb[rowb + c0 + 1]; y1 = yb[rowb + c0 + 1]; }
                }
                u64 a  = pack2(x0, x1);
                u64 bb = pack2(y0, y1);
                u64 ab = mul2(a, bb);
                u64 qq = fma2(a, a, mul2(bb, bb));
                #pragma unroll
                for (int tt = 0; tt < 4; tt++) {
                    int k = j - tt;
                    if (k >= 0 && k <= 10) {
                        u64 wk = w2[(k <= 5) ? k : 10 - k];
                        s0[tt] = fma2(wk, a,  s0[tt]);
                        s1[tt] = fma2(wk, bb, s1[tt]);
                        s2[tt] = fma2(wk, qq, s2[tt]);
                        s3[tt] = fma2(wk, ab, s3[tt]);
                    }
                }
            }
        }
        #pragma unroll
        for (int tt = 0; tt < 4; tt++) {
            unsigned u = (unsigned)(((r0 + tt) * NCP + cp) << 5);
            unsigned su = vb + swz(u);
            sts128(su,       s0[tt], s1[tt]);   // v01 at swz(u)
            sts128(su ^ 16u, s2[tt], s3[tt]);   // v23 at swz(u+16) == swz(u)^16
        }
    }
    __syncthreads();

    // ---- Stage C: horizontal conv + SSIM; 384 units = 24 rows x 16 qblocks,
    //      8-entry window (even alignment), two passes (v01 then v23).
    float lsum = 0.f;
    {
        u64 wS[5], wD[7];
        #pragma unroll
        for (int i = 1; i <= 5; i++) wS[i - 1] = pack2(c_w[2 * i - 1], c_w[2 * i - 1]);
        wD[0] = pack2(0.f, c_w[0]);
        #pragma unroll
        for (int i = 1; i <= 5; i++) wD[i] = pack2(c_w[2 * i - 2], c_w[2 * i]);
        wD[6] = pack2(c_w[10], 0.f);

        const u64 c1_2  = pack2(1e-4f, 1e-4f);
        const u64 c2_2  = pack2(9e-4f, 9e-4f);
        const u64 eps2  = pack2(1e-12f, 1e-12f);
        const u64 n1_2  = pack2(-1.f, -1.f);
        const u64 two_2 = pack2(2.f, 2.f);

        for (int e = tid; e < 24 * 16; e += THREADS) {
            int r  = e >> 4;
            int qb = e & 15;                 // output pairs 2qb, 2qb+1
            unsigned ub = (unsigned)((r * NCP + 2 * qb) << 5);

            u64 pa[8], pb[8];
            // pass 1: v01 window -> mu_x, mu_y
            #pragma unroll
            for (int i = 0; i < 8; i++)
                lds128(vb + swz(ub + (unsigned)(i << 5)), pa[i], pb[i]);

            u64 muxy[2], S[2];
            #pragma unroll
            for (int o = 0; o < 2; o++) {
                u64 mx = hconv_e(pa + o, wS, wD);
                u64 my = hconv_e(pb + o, wS, wD);
                muxy[o] = mul2(mx, my);
                S[o]    = fma2(mx, mx, mul2(my, my));
            }

            // pass 2: v23 window (sub-offset via XOR)
            #pragma unroll
            for (int i = 0; i < 8; i++)
                lds128(vb + (swz(ub + (unsigned)(i << 5)) ^ 16u), pa[i], pb[i]);

            float part = 0.f;
            #pragma unroll
            for (int o = 0; o < 2; o++) {
                u64 m2 = hconv_e(pa + o, wS, wD);
                u64 m3 = hconv_e(pb + o, wS, wD);
                u64 B1 = add2(S[o], c1_2);
                u64 B2 = fma2(n1_2, S[o], add2(m2, c2_2));
                u64 A1 = fma2(two_2, muxy[o], c1_2);
                u64 A2 = fma2(two_2, fma2(n1_2, muxy[o], m3), c2_2);
                u64 num = mul2(A1, A2);
                u64 den = fma2(B1, B2, eps2);
                float nl, nh, dl, dh;
                unpack2(num, nl, nh);
                unpack2(den, dl, dh);
                part += __fdividef(nl, dl) + __fdividef(nh, dh);
            }
            if (ty * TH + r < IMG_H) lsum += part;   // partial-tile guard
        }
    }

    // ---- Block reduction (8 warps) ----
    #pragma unroll
    for (int off = 16; off > 0; off >>= 1)
        lsum += __shfl_down_sync(0xFFFFFFFFu, lsum, off);

    __syncthreads();
    float* red = smem;
    int warp = tid >> 5, lane = tid & 31;
    if (lane == 0) red[warp] = lsum;
    __syncthreads();
    if (warp == 0) {
        float v = (lane < (THREADS / 32)) ? red[lane] : 0.f;
        #pragma unroll
        for (int off = 4; off > 0; off >>= 1)
            v += __shfl_down_sync(0xFFFFFFFFu, v, off);
        if (lane == 0)
            atomicAdd(&g_slots[(blockIdx.x & (NSLOTS - 1)) * SLOT_STRIDE],
                      (double)v);
    }
}

extern "C" void kernel_launch(void* const* d_in, const int* in_sizes, int n_in,
                              void* d_out, int out_size) {
    (void)in_sizes; (void)n_in; (void)out_size;
    const float* x = (const float*)d_in[0];
    const float* y = (const float*)d_in[1];
    float* out = (float*)d_out;

    static bool attr_set = false;
    if (!attr_set) {
        cudaFuncSetAttribute(ssim_main_k,
                             cudaFuncAttributeMaxDynamicSharedMemorySize,
                             SMEM_BYTES);
        attr_set = true;
    }

    ssim_main_k<<<NBLOCKS, THREADS, SMEM_BYTES>>>(x, y);
    ssim_finalize_k<<<1, 32>>>(out);
    ssim_zero_k<<<1, NSLOTS>>>();
}